// round 3
// baseline (speedup 1.0000x reference)
#include <cuda_runtime.h>
#include <cuda_bf16.h>
#include <math.h>

#define KDIR 6
#define HH 64
#define WW 64
#define LL 4096
#define DI 128
#define NS 16
#define DTR 4
#define DM 64

// ---------------- scratch (static device globals; no allocation) ----------------
__device__ float  g_xx[LL * DI];          // conv input, l-major [l][d]
__device__ float  g_z [LL * DI];          // gate branch, l-major
__device__ float  g_xcT[LL * DI];         // conv output (silu), l-major [l][d]
__device__ float  g_dtlow[KDIR * DTR * LL];
__device__ float2 g_BC[KDIR * LL * NS];   // (B,C) packed, [k][t][n]
__device__ float2 g_dd[KDIR * DI * LL];   // (delta, delta*u) packed, [k][d][t]
__device__ float  g_u [KDIR * DI * LL];   // permuted conv output, [k][d][t]
__device__ float  g_y [KDIR * LL * DI];   // scan outputs, [k][t][d]
__device__ int    g_sin [KDIR * LL];      // input spatial index per (k,t)
__device__ int    g_iout[KDIR * LL];      // gather index per (k, out spatial j)
__device__ int    g_rev [LL];
__device__ int    g_diag[LL];

// ---------------- permutation tables ----------------
__global__ void k_tab_a() {
    int j = blockIdx.x * 256 + threadIdx.x;
    if (j >= LL) return;
    int i = j >> 6, c = j & 63, dg = i + c;
    int cum = (dg < 64) ? (dg * (dg + 1)) / 2
                        : 4096 - ((127 - dg) * (128 - dg)) / 2;
    int lo = dg - 63; if (lo < 0) lo = 0;
    int rev = cum + (i - lo);
    g_rev[j] = rev;
    g_diag[rev] = j;            // scatter; completed before k_tab_b
}

__global__ void k_tab_b() {
    int t = blockIdx.x * 256 + threadIdx.x;
    if (t >= LL) return;
    int tr  = (t & 63) * 64 + (t >> 6);
    int t2  = 4095 - t;
    int tr2 = (t2 & 63) * 64 + (t2 >> 6);
    int dg  = g_diag[t];
    g_sin[0 * LL + t] = t;
    g_sin[1 * LL + t] = tr;
    g_sin[2 * LL + t] = t2;
    g_sin[3 * LL + t] = tr2;
    g_sin[4 * LL + t] = dg;
    g_sin[5 * LL + t] = (dg & ~63) | (63 - (dg & 63));
    g_iout[0 * LL + t] = t;
    g_iout[1 * LL + t] = tr;
    g_iout[2 * LL + t] = t2;
    g_iout[3 * LL + t] = 4095 - tr;
    g_iout[4 * LL + t] = g_rev[t];
    g_iout[5 * LL + t] = g_rev[4095 - t];
}

// ---------------- in_proj GEMM: xz[l][o] = x[l][:] . W_in[o][:] ----------------
__global__ void __launch_bounds__(256) k_inproj(const float* __restrict__ x,
                                                const float* __restrict__ W_in) {
    __shared__ float Wsm[128 * 65];
    __shared__ float xsm[32 * 65];
    int tid = threadIdx.x;
    int l0 = blockIdx.x * 32;
    for (int i = tid; i < 32 * 64; i += 256)
        xsm[(i >> 6) * 65 + (i & 63)] = x[(l0 + (i >> 6)) * 64 + (i & 63)];
    int og = tid & 31;
    int lg = tid >> 5;   // 0..7
    for (int ot = 0; ot < 2; ot++) {
        __syncthreads();
        for (int i = tid; i < 128 * 64; i += 256)
            Wsm[(i >> 6) * 65 + (i & 63)] = W_in[(ot * 128 + (i >> 6)) * 64 + (i & 63)];
        __syncthreads();
        float acc[4][4];
        #pragma unroll
        for (int i = 0; i < 4; i++)
            #pragma unroll
            for (int ii = 0; ii < 4; ii++) acc[i][ii] = 0.f;
        for (int c = 0; c < 64; c++) {
            float wv[4], xv[4];
            #pragma unroll
            for (int i = 0; i < 4; i++)  wv[i]  = Wsm[(og + 32 * i) * 65 + c];
            #pragma unroll
            for (int ii = 0; ii < 4; ii++) xv[ii] = xsm[(lg + 8 * ii) * 65 + c];
            #pragma unroll
            for (int i = 0; i < 4; i++)
                #pragma unroll
                for (int ii = 0; ii < 4; ii++)
                    acc[i][ii] = fmaf(wv[i], xv[ii], acc[i][ii]);
        }
        float* dst = (ot == 0) ? g_xx : g_z;
        #pragma unroll
        for (int i = 0; i < 4; i++)
            #pragma unroll
            for (int ii = 0; ii < 4; ii++)
                dst[(l0 + lg + 8 * ii) * 128 + og + 32 * i] = acc[i][ii];
    }
}

// ---------------- depthwise 3x3 conv + bias + SiLU ----------------
__global__ void k_conv(const float* __restrict__ conv_w,
                       const float* __restrict__ conv_b) {
    int idx = blockIdx.x * 256 + threadIdx.x;    // < LL*DI
    int d = idx & 127;
    int l = idx >> 7;
    int h = l >> 6, w = l & 63;
    float acc = conv_b[d];
    #pragma unroll
    for (int kh = -1; kh <= 1; kh++) {
        int hh = h + kh;
        if ((unsigned)hh >= 64u) continue;
        #pragma unroll
        for (int kw = -1; kw <= 1; kw++) {
            int wc = w + kw;
            if ((unsigned)wc >= 64u) continue;
            acc = fmaf(conv_w[d * 9 + (kh + 1) * 3 + (kw + 1)],
                       g_xx[((hh << 6) | wc) * 128 + d], acc);
        }
    }
    g_xcT[l * 128 + d] = acc / (1.f + __expf(-acc));   // silu
}

// ---------------- projection: x_dbl = P[k] @ xs, emit dtlow/B/C + permuted u ----------------
__global__ void __launch_bounds__(256) k_proj(const float* __restrict__ x_proj_w) {
    __shared__ float xs[32][129];
    __shared__ float Ps[36 * 128];
    int k  = blockIdx.y;
    int t0 = blockIdx.x * 32;
    int tid = threadIdx.x;
    for (int i = tid; i < 36 * 128; i += 256)
        Ps[i] = x_proj_w[k * 36 * 128 + i];
    // gather 32 xs rows (one row = 128 contiguous floats of xcT at permuted spatial)
    {
        int lane = tid & 31;
        for (int r = tid >> 5; r < 32; r += 8) {
            int s = g_sin[k * LL + (t0 + r)];
            const float4* src = (const float4*)(g_xcT + s * 128);
            float4 v = src[lane];
            xs[r][lane * 4 + 0] = v.x;
            xs[r][lane * 4 + 1] = v.y;
            xs[r][lane * 4 + 2] = v.z;
            xs[r][lane * 4 + 3] = v.w;
        }
    }
    __syncthreads();
    // emit permuted u [k][d][t] (coalesced along t)
    {
        int tt = tid & 31;
        int wd = tid >> 5;
        for (int d0 = 0; d0 < 128; d0 += 8) {
            int d = d0 + wd;
            g_u[(k * 128 + d) * LL + t0 + tt] = xs[tt][d];
        }
    }
    // compute 36 x 32 projections
    if (tid < 192) {
        int cg = tid >> 4;   // 0..11 (3 c's each)
        int tg = tid & 15;   // 0..15 (2 t's each)
        float acc[3][2] = {{0.f,0.f},{0.f,0.f},{0.f,0.f}};
        for (int dd = 0; dd < 128; dd++) {
            float b0 = xs[tg * 2 + 0][dd];
            float b1 = xs[tg * 2 + 1][dd];
            #pragma unroll
            for (int i = 0; i < 3; i++) {
                float a = Ps[(cg * 3 + i) * 128 + dd];
                acc[i][0] = fmaf(a, b0, acc[i][0]);
                acc[i][1] = fmaf(a, b1, acc[i][1]);
            }
        }
        #pragma unroll
        for (int i = 0; i < 3; i++)
            #pragma unroll
            for (int j = 0; j < 2; j++) {
                int c = cg * 3 + i;
                int t = t0 + tg * 2 + j;
                float v = acc[i][j];
                if (c < 4)       g_dtlow[(k * 4 + c) * LL + t] = v;
                else if (c < 20) g_BC[(k * LL + t) * NS + (c - 4)].x = v;
                else             g_BC[(k * LL + t) * NS + (c - 20)].y = v;
            }
    }
}

// ---------------- delta: dt_rank expansion + softplus; pack (delta, delta*u) ----------------
__global__ void k_delta(const float* __restrict__ dt_w,
                        const float* __restrict__ dt_b) {
    int idx = blockIdx.x * 256 + threadIdx.x;   // < KDIR*DI*LL
    int t = idx & 4095;
    int d = (idx >> 12) & 127;
    int k = idx >> 19;
    float acc = dt_b[k * 128 + d];
    #pragma unroll
    for (int r = 0; r < 4; r++)
        acc = fmaf(dt_w[(k * 128 + d) * 4 + r], g_dtlow[(k * 4 + r) * LL + t], acc);
    float delta = (acc > 20.f) ? acc : log1pf(__expf(acc));
    float u = g_u[idx];
    g_dd[idx] = make_float2(delta, delta * u);
}

// ---------------- selective scan: 384 warps, 2 channels/warp, lane = state n ----------------
__global__ void __launch_bounds__(128, 1) k_scan(const float* __restrict__ A_logs) {
    int warp = blockIdx.x * 4 + (threadIdx.x >> 5);   // 0..383
    int ln = threadIdx.x & 31;
    int k  = warp >> 6;
    int dp = warp & 63;
    int half = ln >> 4;
    int n = ln & 15;
    int d = dp + (half << 6);

    const float2* pBC = g_BC + (size_t)(k * LL) * NS + n;       // step stride NS
    const float2* pDD = g_dd + (size_t)(k * 128 + d) * LL;      // step stride 1
    float*        pY  = g_y  + (size_t)(k * LL) * 128 + d;      // step stride 128

    float A  = -expf(A_logs[(k * 128 + d) * 16 + n]);
    float cA = A * 1.44269504f;   // for ex2
    float x = 0.f;
    float ysave = 0.f;

    for (int t0 = 0; t0 < LL; t0 += 16) {
        #pragma unroll
        for (int s = 0; s < 16; s++) {
            int t = t0 + s;
            float2 bc = pBC[t * NS];
            float2 dd = pDD[t];
            float dA;
            asm("ex2.approx.ftz.f32 %0, %1;" : "=f"(dA) : "f"(dd.x * cA));
            x = fmaf(dA, x, dd.y * bc.x);
            float y = x * bc.y;
            y += __shfl_xor_sync(0xffffffffu, y, 1);
            y += __shfl_xor_sync(0xffffffffu, y, 2);
            y += __shfl_xor_sync(0xffffffffu, y, 4);
            y += __shfl_xor_sync(0xffffffffu, y, 8);
            if (n == s) ysave = y;
        }
        pY[(size_t)(t0 + n) * 128] = ysave;   // 1 STG per warp per 16 steps
    }
}

// ---------------- combine + D-skip + LayerNorm + gate + out_proj ----------------
__global__ void __launch_bounds__(128) k_comb(const float* __restrict__ Ds,
                                              const float* __restrict__ ln_g,
                                              const float* __restrict__ ln_b,
                                              const float* __restrict__ W_out,
                                              float* __restrict__ out) {
    __shared__ float Wsm[64 * 129];
    __shared__ float gsm[128];
    __shared__ float red[8];
    __shared__ float mus[2];
    int tid = threadIdx.x;
    for (int i = tid; i < 64 * 128; i += 128)
        Wsm[(i >> 7) * 129 + (i & 127)] = W_out[i];
    int d = tid;
    float dsum = 0.f;
    #pragma unroll
    for (int k = 0; k < 5; k++) dsum += Ds[k * 128 + d];
    float d5 = Ds[5 * 128 + d];
    float gg = ln_g[d], bb = ln_b[d];
    __syncthreads();

    for (int jj = 0; jj < 16; jj++) {
        int j = blockIdx.x * 16 + jj;
        float y = 0.f;
        #pragma unroll
        for (int k = 0; k < 6; k++)
            y += g_y[(size_t)(k * LL + g_iout[k * LL + j]) * 128 + d];
        int fl = ((63 - (j >> 6)) << 6) | (j & 63);
        y += dsum * g_xcT[j * 128 + d] + d5 * g_xcT[fl * 128 + d];
        // block LayerNorm over 128
        float s1 = y, s2 = y * y;
        #pragma unroll
        for (int o = 16; o; o >>= 1) {
            s1 += __shfl_xor_sync(0xffffffffu, s1, o);
            s2 += __shfl_xor_sync(0xffffffffu, s2, o);
        }
        if ((tid & 31) == 0) { red[tid >> 5] = s1; red[4 + (tid >> 5)] = s2; }
        __syncthreads();
        if (tid == 0) {
            float S1 = red[0] + red[1] + red[2] + red[3];
            float S2 = red[4] + red[5] + red[6] + red[7];
            float mu = S1 * (1.f / 128.f);
            float var = S2 * (1.f / 128.f) - mu * mu;
            mus[0] = mu;
            mus[1] = rsqrtf(var + 1e-5f);
        }
        __syncthreads();
        float yn = (y - mus[0]) * mus[1] * gg + bb;
        float z = g_z[j * 128 + d];
        gsm[d] = yn * (z / (1.f + __expf(-z)));
        __syncthreads();
        if (tid < 64) {
            float acc = 0.f;
            #pragma unroll 8
            for (int dd = 0; dd < 128; dd++)
                acc = fmaf(Wsm[tid * 129 + dd], gsm[dd], acc);
            out[j * 64 + tid] = acc;
        }
        __syncthreads();
    }
}

// ---------------- launch ----------------
extern "C" void kernel_launch(void* const* d_in, const int* in_sizes, int n_in,
                              void* d_out, int out_size) {
    const float* x        = (const float*)d_in[0];
    const float* W_in     = (const float*)d_in[1];
    const float* conv_w   = (const float*)d_in[2];
    const float* conv_b   = (const float*)d_in[3];
    const float* x_proj_w = (const float*)d_in[4];
    const float* dt_w     = (const float*)d_in[5];
    const float* dt_b     = (const float*)d_in[6];
    const float* A_logs   = (const float*)d_in[7];
    const float* Ds       = (const float*)d_in[8];
    const float* ln_g     = (const float*)d_in[9];
    const float* ln_b     = (const float*)d_in[10];
    const float* W_out    = (const float*)d_in[11];
    float* out = (float*)d_out;

    k_tab_a<<<16, 256>>>();
    k_tab_b<<<16, 256>>>();
    k_inproj<<<128, 256>>>(x, W_in);
    k_conv<<<(LL * DI) / 256, 256>>>(conv_w, conv_b);
    {
        dim3 g(LL / 32, KDIR);
        k_proj<<<g, 256>>>(x_proj_w);
    }
    k_delta<<<(KDIR * DI * LL) / 256, 256>>>(dt_w, dt_b);
    k_scan<<<96, 128>>>(A_logs);
    k_comb<<<256, 128>>>(Ds, ln_g, ln_b, W_out, out);
}

// round 4
// speedup vs baseline: 1.3357x; 1.3357x over previous
#include <cuda_runtime.h>
#include <cuda_bf16.h>
#include <math.h>

#define KDIR 6
#define HH 64
#define WW 64
#define LL 4096
#define DI 128
#define NS 16
#define DTR 4
#define DM 64
#define NCH (KDIR * DI)        // 768 channels
#define CHK 32                 // time chunks
#define LC  (LL / CHK)         // 128 steps per chunk

// ---------------- scratch (static device globals; no allocation) ----------------
__device__ float  g_xx[LL * DI];          // conv input, l-major [l][d]
__device__ float  g_z [LL * DI];          // gate branch, l-major
__device__ float  g_xcT[LL * DI];         // conv output (silu), l-major [l][d]
__device__ float  g_dtlow[KDIR * DTR * LL];
__device__ float2 g_BC[KDIR * LL * NS];   // (B,C) packed, [k][t][n]
__device__ float2 g_dd[KDIR * DI * LL];   // (delta, delta*u) packed, [k][d][t]
__device__ float  g_u [KDIR * DI * LL];   // permuted conv output, [k][d][t]
__device__ float  g_y [KDIR * LL * DI];   // scan outputs, [k][t][d]
__device__ float2 g_chk [NCH * CHK * NS]; // per-chunk (xf, aprod)
__device__ float  g_init[NCH * CHK * NS]; // per-chunk initial state
__device__ int    g_sin [KDIR * LL];      // input spatial index per (k,t)
__device__ int    g_iout[KDIR * LL];      // gather index per (k, out spatial j)
__device__ int    g_rev [LL];
__device__ int    g_diag[LL];

// ---------------- permutation tables ----------------
__global__ void k_tab_a() {
    int j = blockIdx.x * 256 + threadIdx.x;
    if (j >= LL) return;
    int i = j >> 6, c = j & 63, dg = i + c;
    int cum = (dg < 64) ? (dg * (dg + 1)) / 2
                        : 4096 - ((127 - dg) * (128 - dg)) / 2;
    int lo = dg - 63; if (lo < 0) lo = 0;
    int rev = cum + (i - lo);
    g_rev[j] = rev;
    g_diag[rev] = j;
}

__global__ void k_tab_b() {
    int t = blockIdx.x * 256 + threadIdx.x;
    if (t >= LL) return;
    int tr  = (t & 63) * 64 + (t >> 6);
    int t2  = 4095 - t;
    int tr2 = (t2 & 63) * 64 + (t2 >> 6);
    int dg  = g_diag[t];
    g_sin[0 * LL + t] = t;
    g_sin[1 * LL + t] = tr;
    g_sin[2 * LL + t] = t2;
    g_sin[3 * LL + t] = tr2;
    g_sin[4 * LL + t] = dg;
    g_sin[5 * LL + t] = (dg & ~63) | (63 - (dg & 63));
    g_iout[0 * LL + t] = t;
    g_iout[1 * LL + t] = tr;
    g_iout[2 * LL + t] = t2;
    g_iout[3 * LL + t] = 4095 - tr;
    g_iout[4 * LL + t] = g_rev[t];
    g_iout[5 * LL + t] = g_rev[4095 - t];
}

// ---------------- in_proj GEMM ----------------
__global__ void __launch_bounds__(256) k_inproj(const float* __restrict__ x,
                                                const float* __restrict__ W_in) {
    __shared__ float Wsm[128 * 65];
    __shared__ float xsm[32 * 65];
    int tid = threadIdx.x;
    int l0 = blockIdx.x * 32;
    for (int i = tid; i < 32 * 64; i += 256)
        xsm[(i >> 6) * 65 + (i & 63)] = x[(l0 + (i >> 6)) * 64 + (i & 63)];
    int og = tid & 31;
    int lg = tid >> 5;
    for (int ot = 0; ot < 2; ot++) {
        __syncthreads();
        for (int i = tid; i < 128 * 64; i += 256)
            Wsm[(i >> 6) * 65 + (i & 63)] = W_in[(ot * 128 + (i >> 6)) * 64 + (i & 63)];
        __syncthreads();
        float acc[4][4];
        #pragma unroll
        for (int i = 0; i < 4; i++)
            #pragma unroll
            for (int ii = 0; ii < 4; ii++) acc[i][ii] = 0.f;
        for (int c = 0; c < 64; c++) {
            float wv[4], xv[4];
            #pragma unroll
            for (int i = 0; i < 4; i++)  wv[i]  = Wsm[(og + 32 * i) * 65 + c];
            #pragma unroll
            for (int ii = 0; ii < 4; ii++) xv[ii] = xsm[(lg + 8 * ii) * 65 + c];
            #pragma unroll
            for (int i = 0; i < 4; i++)
                #pragma unroll
                for (int ii = 0; ii < 4; ii++)
                    acc[i][ii] = fmaf(wv[i], xv[ii], acc[i][ii]);
        }
        float* dst = (ot == 0) ? g_xx : g_z;
        #pragma unroll
        for (int i = 0; i < 4; i++)
            #pragma unroll
            for (int ii = 0; ii < 4; ii++)
                dst[(l0 + lg + 8 * ii) * 128 + og + 32 * i] = acc[i][ii];
    }
}

// ---------------- depthwise 3x3 conv + bias + SiLU ----------------
__global__ void k_conv(const float* __restrict__ conv_w,
                       const float* __restrict__ conv_b) {
    int idx = blockIdx.x * 256 + threadIdx.x;
    int d = idx & 127;
    int l = idx >> 7;
    int h = l >> 6, w = l & 63;
    float acc = conv_b[d];
    #pragma unroll
    for (int kh = -1; kh <= 1; kh++) {
        int hh = h + kh;
        if ((unsigned)hh >= 64u) continue;
        #pragma unroll
        for (int kw = -1; kw <= 1; kw++) {
            int wc = w + kw;
            if ((unsigned)wc >= 64u) continue;
            acc = fmaf(conv_w[d * 9 + (kh + 1) * 3 + (kw + 1)],
                       g_xx[((hh << 6) | wc) * 128 + d], acc);
        }
    }
    g_xcT[l * 128 + d] = acc / (1.f + __expf(-acc));
}

// ---------------- projection ----------------
__global__ void __launch_bounds__(256) k_proj(const float* __restrict__ x_proj_w) {
    __shared__ float xs[32][129];
    __shared__ float Ps[36 * 128];
    int k  = blockIdx.y;
    int t0 = blockIdx.x * 32;
    int tid = threadIdx.x;
    for (int i = tid; i < 36 * 128; i += 256)
        Ps[i] = x_proj_w[k * 36 * 128 + i];
    {
        int lane = tid & 31;
        for (int r = tid >> 5; r < 32; r += 8) {
            int s = g_sin[k * LL + (t0 + r)];
            const float4* src = (const float4*)(g_xcT + s * 128);
            float4 v = src[lane];
            xs[r][lane * 4 + 0] = v.x;
            xs[r][lane * 4 + 1] = v.y;
            xs[r][lane * 4 + 2] = v.z;
            xs[r][lane * 4 + 3] = v.w;
        }
    }
    __syncthreads();
    {
        int tt = tid & 31;
        int wd = tid >> 5;
        for (int d0 = 0; d0 < 128; d0 += 8) {
            int d = d0 + wd;
            g_u[(k * 128 + d) * LL + t0 + tt] = xs[tt][d];
        }
    }
    if (tid < 192) {
        int cg = tid >> 4;
        int tg = tid & 15;
        float acc[3][2] = {{0.f,0.f},{0.f,0.f},{0.f,0.f}};
        for (int dd = 0; dd < 128; dd++) {
            float b0 = xs[tg * 2 + 0][dd];
            float b1 = xs[tg * 2 + 1][dd];
            #pragma unroll
            for (int i = 0; i < 3; i++) {
                float a = Ps[(cg * 3 + i) * 128 + dd];
                acc[i][0] = fmaf(a, b0, acc[i][0]);
                acc[i][1] = fmaf(a, b1, acc[i][1]);
            }
        }
        #pragma unroll
        for (int i = 0; i < 3; i++)
            #pragma unroll
            for (int j = 0; j < 2; j++) {
                int c = cg * 3 + i;
                int t = t0 + tg * 2 + j;
                float v = acc[i][j];
                if (c < 4)       g_dtlow[(k * 4 + c) * LL + t] = v;
                else if (c < 20) g_BC[(k * LL + t) * NS + (c - 4)].x = v;
                else             g_BC[(k * LL + t) * NS + (c - 20)].y = v;
            }
    }
}

// ---------------- delta ----------------
__global__ void k_delta(const float* __restrict__ dt_w,
                        const float* __restrict__ dt_b) {
    int idx = blockIdx.x * 256 + threadIdx.x;
    int t = idx & 4095;
    int d = (idx >> 12) & 127;
    int k = idx >> 19;
    float acc = dt_b[k * 128 + d];
    #pragma unroll
    for (int r = 0; r < 4; r++)
        acc = fmaf(dt_w[(k * 128 + d) * 4 + r], g_dtlow[(k * 4 + r) * LL + t], acc);
    float delta = (acc > 20.f) ? acc : log1pf(__expf(acc));
    float u = g_u[idx];
    g_dd[idx] = make_float2(delta, delta * u);
}

// ---------------- scan pass 1: per-chunk (xf, aprod), no reduction ----------------
__global__ void __launch_bounds__(128) k_scan1(const float* __restrict__ A_logs) {
    int warp = blockIdx.x * 4 + (threadIdx.x >> 5);   // 0 .. 384*CHK-1
    int ln = threadIdx.x & 31;
    int chunk = warp & (CHK - 1);
    int wch   = warp >> 5;        // 0..383 (since CHK=32)
    int k  = wch >> 6;
    int dp = wch & 63;
    int half = ln >> 4;
    int n = ln & 15;
    int d = dp + (half << 6);
    int ch = k * 128 + d;

    const float2* pBC = g_BC + (size_t)(k * LL) * NS + n;
    const float2* pDD = g_dd + (size_t)ch * LL;

    float cA = -expf(A_logs[ch * 16 + n]) * 1.44269504f;
    float x = 0.f, ap = 1.f;
    int tbeg = chunk * LC;
    #pragma unroll 4
    for (int s = 0; s < LC; s++) {
        int t = tbeg + s;
        float2 bc = pBC[(size_t)t * NS];
        float2 dd = pDD[t];
        float dA;
        asm("ex2.approx.ftz.f32 %0, %1;" : "=f"(dA) : "f"(dd.x * cA));
        x = fmaf(dA, x, dd.y * bc.x);
        ap *= dA;
    }
    g_chk[((size_t)ch * CHK + chunk) * NS + n] = make_float2(x, ap);
}

// ---------------- scan pass 2: combine chunk summaries -> initial states ----------------
__global__ void k_scan2() {
    int idx = blockIdx.x * 256 + threadIdx.x;   // < NCH*NS
    if (idx >= NCH * NS) return;
    int ch = idx >> 4;
    int n  = idx & 15;
    float carry = 0.f;
    #pragma unroll
    for (int c = 0; c < CHK; c++) {
        size_t off = ((size_t)ch * CHK + c) * NS + n;
        float2 f = g_chk[off];
        g_init[off] = carry;
        carry = fmaf(f.y, carry, f.x);
    }
}

// ---------------- scan pass 3: full scan with correct init, emit y ----------------
__global__ void __launch_bounds__(128) k_scan3(const float* __restrict__ A_logs) {
    int warp = blockIdx.x * 4 + (threadIdx.x >> 5);
    int ln = threadIdx.x & 31;
    int chunk = warp & (CHK - 1);
    int wch   = warp >> 5;
    int k  = wch >> 6;
    int dp = wch & 63;
    int half = ln >> 4;
    int n = ln & 15;
    int d = dp + (half << 6);
    int ch = k * 128 + d;

    const float2* pBC = g_BC + (size_t)(k * LL) * NS + n;
    const float2* pDD = g_dd + (size_t)ch * LL;
    float*        pY  = g_y  + (size_t)(k * LL) * 128 + d;

    float cA = -expf(A_logs[ch * 16 + n]) * 1.44269504f;
    float x = g_init[((size_t)ch * CHK + chunk) * NS + n];
    float ysave = 0.f;
    int tbeg = chunk * LC;

    for (int t0 = tbeg; t0 < tbeg + LC; t0 += 16) {
        #pragma unroll
        for (int s = 0; s < 16; s++) {
            int t = t0 + s;
            float2 bc = pBC[(size_t)t * NS];
            float2 dd = pDD[t];
            float dA;
            asm("ex2.approx.ftz.f32 %0, %1;" : "=f"(dA) : "f"(dd.x * cA));
            x = fmaf(dA, x, dd.y * bc.x);
            float y = x * bc.y;
            y += __shfl_xor_sync(0xffffffffu, y, 1);
            y += __shfl_xor_sync(0xffffffffu, y, 2);
            y += __shfl_xor_sync(0xffffffffu, y, 4);
            y += __shfl_xor_sync(0xffffffffu, y, 8);
            if (n == s) ysave = y;
        }
        pY[(size_t)(t0 + n) * 128] = ysave;
    }
}

// ---------------- combine + D-skip + LayerNorm + gate + out_proj ----------------
__global__ void __launch_bounds__(128) k_comb(const float* __restrict__ Ds,
                                              const float* __restrict__ ln_g,
                                              const float* __restrict__ ln_b,
                                              const float* __restrict__ W_out,
                                              float* __restrict__ out) {
    __shared__ float Wsm[64 * 129];
    __shared__ float gsm[128];
    __shared__ float red[8];
    __shared__ float mus[2];
    int tid = threadIdx.x;
    for (int i = tid; i < 64 * 128; i += 128)
        Wsm[(i >> 7) * 129 + (i & 127)] = W_out[i];
    int d = tid;
    float dsum = 0.f;
    #pragma unroll
    for (int k = 0; k < 5; k++) dsum += Ds[k * 128 + d];
    float d5 = Ds[5 * 128 + d];
    float gg = ln_g[d], bb = ln_b[d];
    __syncthreads();

    for (int jj = 0; jj < 16; jj++) {
        int j = blockIdx.x * 16 + jj;
        float y = 0.f;
        #pragma unroll
        for (int k = 0; k < 6; k++)
            y += g_y[(size_t)(k * LL + g_iout[k * LL + j]) * 128 + d];
        int fl = ((63 - (j >> 6)) << 6) | (j & 63);
        y += dsum * g_xcT[j * 128 + d] + d5 * g_xcT[fl * 128 + d];
        float s1 = y, s2 = y * y;
        #pragma unroll
        for (int o = 16; o; o >>= 1) {
            s1 += __shfl_xor_sync(0xffffffffu, s1, o);
            s2 += __shfl_xor_sync(0xffffffffu, s2, o);
        }
        if ((tid & 31) == 0) { red[tid >> 5] = s1; red[4 + (tid >> 5)] = s2; }
        __syncthreads();
        if (tid == 0) {
            float S1 = red[0] + red[1] + red[2] + red[3];
            float S2 = red[4] + red[5] + red[6] + red[7];
            float mu = S1 * (1.f / 128.f);
            float var = S2 * (1.f / 128.f) - mu * mu;
            mus[0] = mu;
            mus[1] = rsqrtf(var + 1e-5f);
        }
        __syncthreads();
        float yn = (y - mus[0]) * mus[1] * gg + bb;
        float z = g_z[j * 128 + d];
        gsm[d] = yn * (z / (1.f + __expf(-z)));
        __syncthreads();
        if (tid < 64) {
            float acc = 0.f;
            #pragma unroll 8
            for (int dd = 0; dd < 128; dd++)
                acc = fmaf(Wsm[tid * 129 + dd], gsm[dd], acc);
            out[j * 64 + tid] = acc;
        }
        __syncthreads();
    }
}

// ---------------- launch ----------------
extern "C" void kernel_launch(void* const* d_in, const int* in_sizes, int n_in,
                              void* d_out, int out_size) {
    const float* x        = (const float*)d_in[0];
    const float* W_in     = (const float*)d_in[1];
    const float* conv_w   = (const float*)d_in[2];
    const float* conv_b   = (const float*)d_in[3];
    const float* x_proj_w = (const float*)d_in[4];
    const float* dt_w     = (const float*)d_in[5];
    const float* dt_b     = (const float*)d_in[6];
    const float* A_logs   = (const float*)d_in[7];
    const float* Ds       = (const float*)d_in[8];
    const float* ln_g     = (const float*)d_in[9];
    const float* ln_b     = (const float*)d_in[10];
    const float* W_out    = (const float*)d_in[11];
    float* out = (float*)d_out;

    k_tab_a<<<16, 256>>>();
    k_tab_b<<<16, 256>>>();
    k_inproj<<<128, 256>>>(x, W_in);
    k_conv<<<(LL * DI) / 256, 256>>>(conv_w, conv_b);
    {
        dim3 g(LL / 32, KDIR);
        k_proj<<<g, 256>>>(x_proj_w);
    }
    k_delta<<<(KDIR * DI * LL) / 256, 256>>>(dt_w, dt_b);
    k_scan1<<<(384 * CHK) / 4, 128>>>(A_logs);
    k_scan2<<<48, 256>>>();
    k_scan3<<<(384 * CHK) / 4, 128>>>(A_logs);
    k_comb<<<256, 128>>>(Ds, ln_g, ln_b, W_out, out);
}

// round 5
// speedup vs baseline: 1.4424x; 1.0799x over previous
#include <cuda_runtime.h>
#include <cuda_bf16.h>
#include <math.h>

#define KDIR 6
#define LL 4096
#define DI 128
#define NS 16
#define DTR 4
#define NCH (KDIR * DI)
#define CHK 32
#define LC  (LL / CHK)         // 128

// ---------------- scratch ----------------
__device__ float  g_xx[LL * DI];
__device__ float  g_z [LL * DI];
__device__ float  g_xcT[LL * DI];
__device__ float2 g_BC[KDIR * LL * NS];   // (B,C), [k][t][n]
__device__ float2 g_dd[KDIR * DI * LL];   // (delta, delta*u), [k][d][t]
__device__ float  g_y [KDIR * LL * DI];   // [k][t][d]
__device__ float2 g_chk [NCH * CHK * NS];
__device__ float  g_init[NCH * CHK * NS];
__device__ int    g_sin [KDIR * LL];
__device__ int    g_iout[KDIR * LL];
__device__ int    g_rev [LL];
__device__ int    g_diag[LL];

// ---------------- permutation tables ----------------
__global__ void k_tab_a() {
    int j = blockIdx.x * 256 + threadIdx.x;
    if (j >= LL) return;
    int i = j >> 6, c = j & 63, dg = i + c;
    int cum = (dg < 64) ? (dg * (dg + 1)) / 2
                        : 4096 - ((127 - dg) * (128 - dg)) / 2;
    int lo = dg - 63; if (lo < 0) lo = 0;
    int rev = cum + (i - lo);
    g_rev[j] = rev;
    g_diag[rev] = j;
}

__global__ void k_tab_b() {
    int t = blockIdx.x * 256 + threadIdx.x;
    if (t >= LL) return;
    int tr  = (t & 63) * 64 + (t >> 6);
    int t2  = 4095 - t;
    int tr2 = (t2 & 63) * 64 + (t2 >> 6);
    int dg  = g_diag[t];
    g_sin[0 * LL + t] = t;
    g_sin[1 * LL + t] = tr;
    g_sin[2 * LL + t] = t2;
    g_sin[3 * LL + t] = tr2;
    g_sin[4 * LL + t] = dg;
    g_sin[5 * LL + t] = (dg & ~63) | (63 - (dg & 63));
    g_iout[0 * LL + t] = t;
    g_iout[1 * LL + t] = tr;
    g_iout[2 * LL + t] = t2;
    g_iout[3 * LL + t] = 4095 - tr;
    g_iout[4 * LL + t] = g_rev[t];
    g_iout[5 * LL + t] = g_rev[4095 - t];
}

// ---------------- in_proj GEMM ----------------
__global__ void __launch_bounds__(256) k_inproj(const float* __restrict__ x,
                                                const float* __restrict__ W_in) {
    __shared__ float Wsm[128 * 65];
    __shared__ float xsm[32 * 65];
    int tid = threadIdx.x;
    int l0 = blockIdx.x * 32;
    for (int i = tid; i < 32 * 64; i += 256)
        xsm[(i >> 6) * 65 + (i & 63)] = x[(l0 + (i >> 6)) * 64 + (i & 63)];
    int og = tid & 31;
    int lg = tid >> 5;
    for (int ot = 0; ot < 2; ot++) {
        __syncthreads();
        for (int i = tid; i < 128 * 64; i += 256)
            Wsm[(i >> 6) * 65 + (i & 63)] = W_in[(ot * 128 + (i >> 6)) * 64 + (i & 63)];
        __syncthreads();
        float acc[4][4];
        #pragma unroll
        for (int i = 0; i < 4; i++)
            #pragma unroll
            for (int ii = 0; ii < 4; ii++) acc[i][ii] = 0.f;
        for (int c = 0; c < 64; c++) {
            float wv[4], xv[4];
            #pragma unroll
            for (int i = 0; i < 4; i++)  wv[i]  = Wsm[(og + 32 * i) * 65 + c];
            #pragma unroll
            for (int ii = 0; ii < 4; ii++) xv[ii] = xsm[(lg + 8 * ii) * 65 + c];
            #pragma unroll
            for (int i = 0; i < 4; i++)
                #pragma unroll
                for (int ii = 0; ii < 4; ii++)
                    acc[i][ii] = fmaf(wv[i], xv[ii], acc[i][ii]);
        }
        float* dst = (ot == 0) ? g_xx : g_z;
        #pragma unroll
        for (int i = 0; i < 4; i++)
            #pragma unroll
            for (int ii = 0; ii < 4; ii++)
                dst[(l0 + lg + 8 * ii) * 128 + og + 32 * i] = acc[i][ii];
    }
}

// ---------------- depthwise 3x3 conv + bias + SiLU (float2 per thread) ----------------
__global__ void __launch_bounds__(256) k_conv(const float* __restrict__ conv_w,
                                              const float* __restrict__ conv_b) {
    __shared__ float2 cw[9 * 64];
    __shared__ float2 cb[64];
    int tid = threadIdx.x;
    for (int i = tid; i < 9 * 64; i += 256) {
        int tap = i >> 6, d2 = i & 63;
        cw[i] = make_float2(conv_w[(2 * d2) * 9 + tap], conv_w[(2 * d2 + 1) * 9 + tap]);
    }
    if (tid < 64) cb[tid] = ((const float2*)conv_b)[tid];
    __syncthreads();
    int idx = blockIdx.x * 256 + tid;    // < LL*64
    int d2 = idx & 63;
    int l = idx >> 6;
    int h = l >> 6, w = l & 63;
    float2 acc = cb[d2];
    const float2* xx2 = (const float2*)g_xx;
    #pragma unroll
    for (int kh = -1; kh <= 1; kh++) {
        int hh = h + kh;
        if ((unsigned)hh >= 64u) continue;
        #pragma unroll
        for (int kw = -1; kw <= 1; kw++) {
            int wc = w + kw;
            if ((unsigned)wc >= 64u) continue;
            float2 v = xx2[((hh << 6) | wc) * 64 + d2];
            float2 cc = cw[((kh + 1) * 3 + (kw + 1)) * 64 + d2];
            acc.x = fmaf(cc.x, v.x, acc.x);
            acc.y = fmaf(cc.y, v.y, acc.y);
        }
    }
    acc.x = acc.x / (1.f + __expf(-acc.x));
    acc.y = acc.y / (1.f + __expf(-acc.y));
    ((float2*)g_xcT)[l * 64 + d2] = acc;
}

// ---------------- projection + fused delta: emit BC + g_dd directly ----------------
__global__ void __launch_bounds__(256) k_proj(const float* __restrict__ x_proj_w,
                                              const float* __restrict__ dt_w,
                                              const float* __restrict__ dt_b) {
    __shared__ float xs[32][129];
    __shared__ float Ps[36 * 128];
    __shared__ float dts[4][32];
    int k  = blockIdx.y;
    int t0 = blockIdx.x * 32;
    int tid = threadIdx.x;
    for (int i = tid; i < 36 * 128; i += 256)
        Ps[i] = x_proj_w[k * 36 * 128 + i];
    {
        int lane = tid & 31;
        for (int r = tid >> 5; r < 32; r += 8) {
            int s = g_sin[k * LL + (t0 + r)];
            const float4* src = (const float4*)(g_xcT + s * 128);
            float4 v = src[lane];
            xs[r][lane * 4 + 0] = v.x;
            xs[r][lane * 4 + 1] = v.y;
            xs[r][lane * 4 + 2] = v.z;
            xs[r][lane * 4 + 3] = v.w;
        }
    }
    __syncthreads();
    // 36 x 32 projections
    if (tid < 192) {
        int cg = tid >> 4;
        int tg = tid & 15;
        float acc[3][2] = {{0.f,0.f},{0.f,0.f},{0.f,0.f}};
        for (int dd = 0; dd < 128; dd++) {
            float b0 = xs[tg * 2 + 0][dd];
            float b1 = xs[tg * 2 + 1][dd];
            #pragma unroll
            for (int i = 0; i < 3; i++) {
                float a = Ps[(cg * 3 + i) * 128 + dd];
                acc[i][0] = fmaf(a, b0, acc[i][0]);
                acc[i][1] = fmaf(a, b1, acc[i][1]);
            }
        }
        #pragma unroll
        for (int i = 0; i < 3; i++)
            #pragma unroll
            for (int j = 0; j < 2; j++) {
                int c = cg * 3 + i;
                int tl = tg * 2 + j;
                int t = t0 + tl;
                float v = acc[i][j];
                if (c < 4)       dts[c][tl] = v;
                else if (c < 20) g_BC[(size_t)(k * LL + t) * NS + (c - 4)].x = v;
                else             g_BC[(size_t)(k * LL + t) * NS + (c - 20)].y = v;
            }
    }
    __syncthreads();
    // fused delta: 128 d x 32 t; warp covers one d per iteration (coalesced t writes)
    {
        int t = tid & 31;
        int w = tid >> 5;   // 0..7
        #pragma unroll
        for (int it = 0; it < 16; it++) {
            int d = w + 8 * it;
            float acc = dt_b[k * 128 + d];
            #pragma unroll
            for (int r = 0; r < 4; r++)
                acc = fmaf(dt_w[(k * 128 + d) * 4 + r], dts[r][t], acc);
            float delta = (acc > 20.f) ? acc : log1pf(__expf(acc));
            float u = xs[t][d];
            g_dd[(size_t)(k * 128 + d) * LL + t0 + t] = make_float2(delta, delta * u);
        }
    }
}

// ---------------- scan pass 1: per-chunk (xf, aprod) ----------------
__global__ void __launch_bounds__(1024, 1) k_scan1(const float* __restrict__ A_logs) {
    __shared__ float bb[LC * 16];          // B values, 8KB
    int tid = threadIdx.x;
    int wl = tid >> 5;                     // 0..31
    int ln = tid & 31;
    int k = blockIdx.z, chunk = blockIdx.y, xh = blockIdx.x;
    int dp = xh * 32 + wl;
    int half = ln >> 4, n = ln & 15;
    int d = dp + (half << 6);
    int ch = k * 128 + d;
    int tbeg = chunk * LC;

    const float2* srcBC = g_BC + (size_t)(k * LL + tbeg) * NS;
    for (int i = tid; i < LC * 16; i += 1024) bb[i] = srcBC[i].x;
    __syncthreads();

    const float2* pDD = g_dd + (size_t)ch * LL + tbeg;
    float cA = -expf(A_logs[ch * 16 + n]) * 1.44269504f;
    float x = 0.f, ap = 1.f;
    #pragma unroll 4
    for (int s = 0; s < LC; s++) {
        float2 dd = pDD[s];
        float b = bb[s * 16 + n];
        float dA;
        asm("ex2.approx.ftz.f32 %0, %1;" : "=f"(dA) : "f"(dd.x * cA));
        x = fmaf(dA, x, dd.y * b);
        ap *= dA;
    }
    g_chk[((size_t)ch * CHK + chunk) * NS + n] = make_float2(x, ap);
}

// ---------------- scan pass 2: chunk summaries -> initial states ----------------
__global__ void k_scan2() {
    int idx = blockIdx.x * 256 + threadIdx.x;
    if (idx >= NCH * NS) return;
    int ch = idx >> 4;
    int n  = idx & 15;
    float carry = 0.f;
    #pragma unroll
    for (int c = 0; c < CHK; c++) {
        size_t off = ((size_t)ch * CHK + c) * NS + n;
        float2 f = g_chk[off];
        g_init[off] = carry;
        carry = fmaf(f.y, carry, f.x);
    }
}

// ---------------- scan pass 3: emit y, smem-staged coalesced stores ----------------
__global__ void __launch_bounds__(1024, 1) k_scan3(const float* __restrict__ A_logs) {
    __shared__ float2 bcs[LC * 16];        // 16KB
    __shared__ float ytile[16 * 65];
    int tid = threadIdx.x;
    int wl = tid >> 5;
    int ln = tid & 31;
    int k = blockIdx.z, chunk = blockIdx.y, xh = blockIdx.x;
    int dp = xh * 32 + wl;
    int half = ln >> 4, n = ln & 15;
    int d = dp + (half << 6);
    int ch = k * 128 + d;
    int tbeg = chunk * LC;

    {
        const float4* src = (const float4*)(g_BC + (size_t)(k * LL + tbeg) * NS);
        ((float4*)bcs)[tid] = src[tid];    // 2048 float2 = 1024 float4
    }
    __syncthreads();

    const float2* pDD = g_dd + (size_t)ch * LL + tbeg;
    float cA = -expf(A_logs[ch * 16 + n]) * 1.44269504f;
    float x = g_init[((size_t)ch * CHK + chunk) * NS + n];

    int sr = tid >> 6;        // store row 0..15
    int sc = tid & 63;        // store col
    int sd = xh * 32 + (sc & 31) + ((sc >> 5) << 6);
    float* ydst0 = g_y + (size_t)(k * LL + tbeg) * 128 + sd;

    for (int t0 = 0; t0 < LC; t0 += 16) {
        float ysave = 0.f;
        #pragma unroll
        for (int s = 0; s < 16; s++) {
            float2 bc = bcs[(t0 + s) * 16 + n];
            float2 dd = pDD[t0 + s];
            float dA;
            asm("ex2.approx.ftz.f32 %0, %1;" : "=f"(dA) : "f"(dd.x * cA));
            x = fmaf(dA, x, dd.y * bc.x);
            float y = x * bc.y;
            y += __shfl_xor_sync(0xffffffffu, y, 1);
            y += __shfl_xor_sync(0xffffffffu, y, 2);
            y += __shfl_xor_sync(0xffffffffu, y, 4);
            y += __shfl_xor_sync(0xffffffffu, y, 8);
            if (n == s) ysave = y;
        }
        ytile[n * 65 + (half << 5) + wl] = ysave;
        __syncthreads();
        ydst0[(size_t)(t0 + sr) * 128] = ytile[sr * 65 + sc];
        __syncthreads();
    }
}

// ---------------- combine + D-skip + LayerNorm + gate + out_proj ----------------
__global__ void __launch_bounds__(128) k_comb(const float* __restrict__ Ds,
                                              const float* __restrict__ ln_g,
                                              const float* __restrict__ ln_b,
                                              const float* __restrict__ W_out,
                                              float* __restrict__ out) {
    __shared__ float Wsm[64 * 129];
    __shared__ float gsm[128];
    __shared__ float red[8];
    __shared__ float mus[2];
    int tid = threadIdx.x;
    for (int i = tid; i < 64 * 128; i += 128)
        Wsm[(i >> 7) * 129 + (i & 127)] = W_out[i];
    int d = tid;
    float dsum = 0.f;
    #pragma unroll
    for (int k = 0; k < 5; k++) dsum += Ds[k * 128 + d];
    float d5 = Ds[5 * 128 + d];
    float gg = ln_g[d], bb = ln_b[d];
    __syncthreads();

    for (int jj = 0; jj < 16; jj++) {
        int j = blockIdx.x * 16 + jj;
        float y = 0.f;
        #pragma unroll
        for (int k = 0; k < 6; k++)
            y += g_y[(size_t)(k * LL + g_iout[k * LL + j]) * 128 + d];
        int fl = ((63 - (j >> 6)) << 6) | (j & 63);
        y += dsum * g_xcT[j * 128 + d] + d5 * g_xcT[fl * 128 + d];
        float s1 = y, s2 = y * y;
        #pragma unroll
        for (int o = 16; o; o >>= 1) {
            s1 += __shfl_xor_sync(0xffffffffu, s1, o);
            s2 += __shfl_xor_sync(0xffffffffu, s2, o);
        }
        if ((tid & 31) == 0) { red[tid >> 5] = s1; red[4 + (tid >> 5)] = s2; }
        __syncthreads();
        if (tid == 0) {
            float S1 = red[0] + red[1] + red[2] + red[3];
            float S2 = red[4] + red[5] + red[6] + red[7];
            float mu = S1 * (1.f / 128.f);
            float var = S2 * (1.f / 128.f) - mu * mu;
            mus[0] = mu;
            mus[1] = rsqrtf(var + 1e-5f);
        }
        __syncthreads();
        float yn = (y - mus[0]) * mus[1] * gg + bb;
        float z = g_z[j * 128 + d];
        gsm[d] = yn * (z / (1.f + __expf(-z)));
        __syncthreads();
        if (tid < 64) {
            float acc = 0.f;
            #pragma unroll 8
            for (int dd = 0; dd < 128; dd++)
                acc = fmaf(Wsm[tid * 129 + dd], gsm[dd], acc);
            out[j * 64 + tid] = acc;
        }
        __syncthreads();
    }
}

// ---------------- launch ----------------
extern "C" void kernel_launch(void* const* d_in, const int* in_sizes, int n_in,
                              void* d_out, int out_size) {
    const float* x        = (const float*)d_in[0];
    const float* W_in     = (const float*)d_in[1];
    const float* conv_w   = (const float*)d_in[2];
    const float* conv_b   = (const float*)d_in[3];
    const float* x_proj_w = (const float*)d_in[4];
    const float* dt_w     = (const float*)d_in[5];
    const float* dt_b     = (const float*)d_in[6];
    const float* A_logs   = (const float*)d_in[7];
    const float* Ds       = (const float*)d_in[8];
    const float* ln_g     = (const float*)d_in[9];
    const float* ln_b     = (const float*)d_in[10];
    const float* W_out    = (const float*)d_in[11];
    float* out = (float*)d_out;

    k_tab_a<<<16, 256>>>();
    k_tab_b<<<16, 256>>>();
    k_inproj<<<128, 256>>>(x, W_in);
    k_conv<<<(LL * 64) / 256, 256>>>(conv_w, conv_b);
    {
        dim3 g(LL / 32, KDIR);
        k_proj<<<g, 256>>>(x_proj_w, dt_w, dt_b);
    }
    {
        dim3 gs(2, CHK, KDIR);
        k_scan1<<<gs, 1024>>>(A_logs);
        k_scan2<<<48, 256>>>();
        k_scan3<<<gs, 1024>>>(A_logs);
    }
    k_comb<<<256, 128>>>(Ds, ln_g, ln_b, W_out, out);
}

// round 6
// speedup vs baseline: 1.5365x; 1.0653x over previous
#include <cuda_runtime.h>
#include <cuda_bf16.h>
#include <math.h>

#define KDIR 6
#define LL 4096
#define DI 128
#define NS 16
#define DTR 4
#define NCH (KDIR * DI)
#define CHK 32
#define LC  (LL / CHK)         // 128

// ---------------- scratch ----------------
__device__ float  g_xx[LL * DI];
__device__ float  g_z [LL * DI];
__device__ float  g_xcT[LL * DI];
__device__ float2 g_BC[KDIR * LL * NS];   // (B,C), [k][t][n]
__device__ float2 g_dd[KDIR * DI * LL];   // (delta, delta*u), [k][d][t]
__device__ float  g_y [KDIR * LL * DI];   // [k][t][d]
__device__ float2 g_chk [NCH * CHK * NS];
__device__ float  g_init[NCH * CHK * NS];

// ---------------- closed-form diagonal permutation ----------------
__device__ __forceinline__ int dg_low(int r) {
    int dg = (int)((sqrtf((float)(8 * r + 1)) - 1.f) * 0.5f);
    while (((dg + 1) * (dg + 2)) >> 1 <= r) dg++;
    while ((dg * (dg + 1)) >> 1 > r) dg--;
    return dg;
}
// rank r (diagonal order) -> row-major index
__device__ __forceinline__ int diag_t(int r) {
    int i, dg;
    if (r < 2080) { dg = dg_low(r); i = r - ((dg * (dg + 1)) >> 1); }
    else {
        int q = 4095 - r;
        int dgm = dg_low(q);
        int p = q - ((dgm * (dgm + 1)) >> 1);
        i = 63 - p;
        dg = 126 - dgm;
    }
    int j = dg - i;
    return (i << 6) | j;
}
// row-major index -> rank in diagonal order
__device__ __forceinline__ int rev_idx(int t) {
    int i = t >> 6, c = t & 63, dg = i + c;
    int cum = (dg < 64) ? ((dg * (dg + 1)) >> 1)
                        : 4096 - (((127 - dg) * (128 - dg)) >> 1);
    int lo = dg - 63; if (lo < 0) lo = 0;
    return cum + i - lo;
}
__device__ __forceinline__ int sin_idx(int k, int t) {
    switch (k) {
        case 0: return t;
        case 1: return ((t & 63) << 6) | (t >> 6);
        case 2: return 4095 - t;
        case 3: { int t2 = 4095 - t; return ((t2 & 63) << 6) | (t2 >> 6); }
        case 4: return diag_t(t);
        default: return diag_t(t) ^ 63;   // flip W (63-j == 63^j)
    }
}
__device__ __forceinline__ int iout_idx(int k, int j) {
    switch (k) {
        case 0: return j;
        case 1: return ((j & 63) << 6) | (j >> 6);
        case 2: return 4095 - j;
        case 3: return 4095 - (((j & 63) << 6) | (j >> 6));
        case 4: return rev_idx(j);
        default: return rev_idx(4095 - j);
    }
}

// ---------------- in_proj GEMM ----------------
__global__ void __launch_bounds__(256) k_inproj(const float* __restrict__ x,
                                                const float* __restrict__ W_in) {
    __shared__ float Wsm[128 * 65];
    __shared__ float xsm[32 * 65];
    int tid = threadIdx.x;
    int l0 = blockIdx.x * 32;
    for (int i = tid; i < 32 * 64; i += 256)
        xsm[(i >> 6) * 65 + (i & 63)] = x[(l0 + (i >> 6)) * 64 + (i & 63)];
    int og = tid & 31;
    int lg = tid >> 5;
    for (int ot = 0; ot < 2; ot++) {
        __syncthreads();
        for (int i = tid; i < 128 * 64; i += 256)
            Wsm[(i >> 6) * 65 + (i & 63)] = W_in[(ot * 128 + (i >> 6)) * 64 + (i & 63)];
        __syncthreads();
        float acc[4][4];
        #pragma unroll
        for (int i = 0; i < 4; i++)
            #pragma unroll
            for (int ii = 0; ii < 4; ii++) acc[i][ii] = 0.f;
        for (int c = 0; c < 64; c++) {
            float wv[4], xv[4];
            #pragma unroll
            for (int i = 0; i < 4; i++)  wv[i]  = Wsm[(og + 32 * i) * 65 + c];
            #pragma unroll
            for (int ii = 0; ii < 4; ii++) xv[ii] = xsm[(lg + 8 * ii) * 65 + c];
            #pragma unroll
            for (int i = 0; i < 4; i++)
                #pragma unroll
                for (int ii = 0; ii < 4; ii++)
                    acc[i][ii] = fmaf(wv[i], xv[ii], acc[i][ii]);
        }
        float* dst = (ot == 0) ? g_xx : g_z;
        #pragma unroll
        for (int i = 0; i < 4; i++)
            #pragma unroll
            for (int ii = 0; ii < 4; ii++)
                dst[(l0 + lg + 8 * ii) * 128 + og + 32 * i] = acc[i][ii];
    }
}

// ---------------- depthwise 3x3 conv + bias + SiLU ----------------
__global__ void __launch_bounds__(256) k_conv(const float* __restrict__ conv_w,
                                              const float* __restrict__ conv_b) {
    __shared__ float2 cw[9 * 64];
    __shared__ float2 cb[64];
    int tid = threadIdx.x;
    for (int i = tid; i < 9 * 64; i += 256) {
        int tap = i >> 6, d2 = i & 63;
        cw[i] = make_float2(conv_w[(2 * d2) * 9 + tap], conv_w[(2 * d2 + 1) * 9 + tap]);
    }
    if (tid < 64) cb[tid] = ((const float2*)conv_b)[tid];
    __syncthreads();
    int idx = blockIdx.x * 256 + tid;
    int d2 = idx & 63;
    int l = idx >> 6;
    int h = l >> 6, w = l & 63;
    float2 acc = cb[d2];
    const float2* xx2 = (const float2*)g_xx;
    #pragma unroll
    for (int kh = -1; kh <= 1; kh++) {
        int hh = h + kh;
        if ((unsigned)hh >= 64u) continue;
        #pragma unroll
        for (int kw = -1; kw <= 1; kw++) {
            int wc = w + kw;
            if ((unsigned)wc >= 64u) continue;
            float2 v = xx2[((hh << 6) | wc) * 64 + d2];
            float2 cc = cw[((kh + 1) * 3 + (kw + 1)) * 64 + d2];
            acc.x = fmaf(cc.x, v.x, acc.x);
            acc.y = fmaf(cc.y, v.y, acc.y);
        }
    }
    acc.x = acc.x / (1.f + __expf(-acc.x));
    acc.y = acc.y / (1.f + __expf(-acc.y));
    ((float2*)g_xcT)[l * 64 + d2] = acc;
}

// ---------------- projection + fused delta ----------------
__global__ void __launch_bounds__(256) k_proj(const float* __restrict__ x_proj_w,
                                              const float* __restrict__ dt_w,
                                              const float* __restrict__ dt_b) {
    __shared__ float xs[32][129];
    __shared__ float Ps[36 * 128];
    __shared__ float dts[4][32];
    __shared__ int sidx[32];
    int k  = blockIdx.y;
    int t0 = blockIdx.x * 32;
    int tid = threadIdx.x;
    if (tid < 32) sidx[tid] = sin_idx(k, t0 + tid);
    __syncthreads();
    for (int i = tid; i < 36 * 128; i += 256)
        Ps[i] = x_proj_w[k * 36 * 128 + i];
    {
        int lane = tid & 31;
        for (int r = tid >> 5; r < 32; r += 8) {
            int s = sidx[r];
            const float4* src = (const float4*)(g_xcT + s * 128);
            float4 v = src[lane];
            xs[r][lane * 4 + 0] = v.x;
            xs[r][lane * 4 + 1] = v.y;
            xs[r][lane * 4 + 2] = v.z;
            xs[r][lane * 4 + 3] = v.w;
        }
    }
    __syncthreads();
    if (tid < 192) {
        int cg = tid >> 4;
        int tg = tid & 15;
        float acc[3][2] = {{0.f,0.f},{0.f,0.f},{0.f,0.f}};
        for (int dd = 0; dd < 128; dd++) {
            float b0 = xs[tg * 2 + 0][dd];
            float b1 = xs[tg * 2 + 1][dd];
            #pragma unroll
            for (int i = 0; i < 3; i++) {
                float a = Ps[(cg * 3 + i) * 128 + dd];
                acc[i][0] = fmaf(a, b0, acc[i][0]);
                acc[i][1] = fmaf(a, b1, acc[i][1]);
            }
        }
        #pragma unroll
        for (int i = 0; i < 3; i++)
            #pragma unroll
            for (int j = 0; j < 2; j++) {
                int c = cg * 3 + i;
                int tl = tg * 2 + j;
                int t = t0 + tl;
                float v = acc[i][j];
                if (c < 4)       dts[c][tl] = v;
                else if (c < 20) g_BC[(size_t)(k * LL + t) * NS + (c - 4)].x = v;
                else             g_BC[(size_t)(k * LL + t) * NS + (c - 20)].y = v;
            }
    }
    __syncthreads();
    {
        int t = tid & 31;
        int w = tid >> 5;
        #pragma unroll
        for (int it = 0; it < 16; it++) {
            int d = w + 8 * it;
            float acc = dt_b[k * 128 + d];
            #pragma unroll
            for (int r = 0; r < 4; r++)
                acc = fmaf(dt_w[(k * 128 + d) * 4 + r], dts[r][t], acc);
            float delta = (acc > 20.f) ? acc : log1pf(__expf(acc));
            float u = xs[t][d];
            g_dd[(size_t)(k * 128 + d) * LL + t0 + t] = make_float2(delta, delta * u);
        }
    }
}

// ---------------- scan pass 1: per-chunk (xf, aprod) via sum-of-delta ----------------
__global__ void __launch_bounds__(1024) k_scan1(const float* __restrict__ A_logs) {
    __shared__ float bb[LC * 16];
    int tid = threadIdx.x;
    int wl = tid >> 5;
    int ln = tid & 31;
    int k = blockIdx.z, chunk = blockIdx.y, xh = blockIdx.x;
    int dp = xh * 32 + wl;
    int half = ln >> 4, n = ln & 15;
    int d = dp + (half << 6);
    int ch = k * 128 + d;
    int tbeg = chunk * LC;

    const float2* srcBC = g_BC + (size_t)(k * LL + tbeg) * NS;
    for (int i = tid; i < LC * 16; i += 1024) bb[i] = srcBC[i].x;
    __syncthreads();

    const float2* pDD = g_dd + (size_t)ch * LL + tbeg;
    float cA = -expf(A_logs[ch * 16 + n]) * 1.44269504f;
    float x = 0.f, sdelta = 0.f;
    #pragma unroll 4
    for (int s = 0; s < LC; s++) {
        float2 dd = pDD[s];
        float b = bb[s * 16 + n];
        float dA;
        asm("ex2.approx.ftz.f32 %0, %1;" : "=f"(dA) : "f"(dd.x * cA));
        x = fmaf(dA, x, dd.y * b);
        sdelta += dd.x;
    }
    float ap;
    asm("ex2.approx.ftz.f32 %0, %1;" : "=f"(ap) : "f"(sdelta * cA));
    g_chk[((size_t)ch * CHK + chunk) * NS + n] = make_float2(x, ap);
}

// ---------------- scan pass 2: chunk summaries -> initial states ----------------
__global__ void k_scan2() {
    int idx = blockIdx.x * 256 + threadIdx.x;
    if (idx >= NCH * NS) return;
    int ch = idx >> 4;
    int n  = idx & 15;
    float carry = 0.f;
    #pragma unroll
    for (int c = 0; c < CHK; c++) {
        size_t off = ((size_t)ch * CHK + c) * NS + n;
        float2 f = g_chk[off];
        g_init[off] = carry;
        carry = fmaf(f.y, carry, f.x);
    }
}

// ---------------- scan pass 3: smem transpose-reduce, coalesced y ----------------
__global__ void __launch_bounds__(1024) k_scan3(const float* __restrict__ A_logs) {
    __shared__ float xc[32][8][33];    // per-warp x*C tile, 33.8 KB
    __shared__ float ytile[8 * 65];    // 2 KB
    int tid = threadIdx.x;
    int wl = tid >> 5;
    int ln = tid & 31;
    int k = blockIdx.z, chunk = blockIdx.y, xh = blockIdx.x;
    int dp = xh * 32 + wl;
    int half = ln >> 4, n = ln & 15;
    int d = dp + (half << 6);
    int ch = k * 128 + d;
    int tbeg = chunk * LC;

    const float2* pBC = g_BC + (size_t)(k * LL + tbeg) * NS + n;
    const float2* pDD = g_dd + (size_t)ch * LL + tbeg;
    float cA = -expf(A_logs[ch * 16 + n]) * 1.44269504f;
    float x = g_init[((size_t)ch * CHK + chunk) * NS + n];

    // reduce-phase lane mapping
    int rc = ln >> 4;          // channel half
    int rj = (ln >> 1) & 7;    // t within window
    int rh = ln & 1;           // n-subgroup
    // store-phase mapping
    int sr = tid >> 6;         // 0..15 (only 0..7 used)
    int sc = tid & 63;
    int sd = xh * 32 + (sc & 31) + ((sc >> 5) << 6);
    float* ydst0 = g_y + (size_t)(k * LL + tbeg) * 128 + sd;

    for (int t0 = 0; t0 < LC; t0 += 8) {
        #pragma unroll
        for (int s = 0; s < 8; s++) {
            float2 bc = pBC[(size_t)(t0 + s) * NS];
            float2 dd = pDD[t0 + s];
            float dA;
            asm("ex2.approx.ftz.f32 %0, %1;" : "=f"(dA) : "f"(dd.x * cA));
            x = fmaf(dA, x, dd.y * bc.x);
            xc[wl][s][ln] = x * bc.y;
        }
        __syncwarp();
        float sum = 0.f;
        #pragma unroll
        for (int m = 0; m < 8; m++)
            sum += xc[wl][rj][rc * 16 + rh * 8 + m];
        sum += __shfl_xor_sync(0xffffffffu, sum, 1);
        if (rh == 0) ytile[rj * 65 + rc * 32 + wl] = sum;
        __syncthreads();
        if (tid < 512) ydst0[(size_t)(t0 + sr) * 128] = ytile[sr * 65 + sc];
        __syncthreads();
    }
}

// ---------------- combine + D-skip + LayerNorm + gate + out_proj ----------------
__global__ void __launch_bounds__(128) k_comb(const float* __restrict__ Ds,
                                              const float* __restrict__ ln_g,
                                              const float* __restrict__ ln_b,
                                              const float* __restrict__ W_out,
                                              float* __restrict__ out) {
    __shared__ float Wsm[64 * 129];
    __shared__ float gsm[128];
    __shared__ float red[8];
    __shared__ float mus[2];
    __shared__ int ism[6 * 16];
    int tid = threadIdx.x;
    for (int i = tid; i < 64 * 128; i += 128)
        Wsm[(i >> 7) * 129 + (i & 127)] = W_out[i];
    if (tid < 96) {
        int kk = tid >> 4, jj = tid & 15;
        ism[kk * 16 + jj] = iout_idx(kk, blockIdx.x * 16 + jj);
    }
    int d = tid;
    float dsum = 0.f;
    #pragma unroll
    for (int k = 0; k < 5; k++) dsum += Ds[k * 128 + d];
    float d5 = Ds[5 * 128 + d];
    float gg = ln_g[d], bb = ln_b[d];
    int lane = tid & 31;
    int oo = (tid >> 5) * 16 + (lane & 15);   // output index 0..63
    int hh2 = lane >> 4;                      // dot-product half
    __syncthreads();

    for (int jj = 0; jj < 16; jj++) {
        int j = blockIdx.x * 16 + jj;
        float y = 0.f;
        #pragma unroll
        for (int k = 0; k < 6; k++)
            y += g_y[(size_t)(k * LL + ism[k * 16 + jj]) * 128 + d];
        int fl = ((63 - (j >> 6)) << 6) | (j & 63);
        y += dsum * g_xcT[j * 128 + d] + d5 * g_xcT[fl * 128 + d];
        float s1 = y, s2 = y * y;
        #pragma unroll
        for (int o = 16; o; o >>= 1) {
            s1 += __shfl_xor_sync(0xffffffffu, s1, o);
            s2 += __shfl_xor_sync(0xffffffffu, s2, o);
        }
        if ((tid & 31) == 0) { red[tid >> 5] = s1; red[4 + (tid >> 5)] = s2; }
        __syncthreads();
        if (tid == 0) {
            float S1 = red[0] + red[1] + red[2] + red[3];
            float S2 = red[4] + red[5] + red[6] + red[7];
            float mu = S1 * (1.f / 128.f);
            float var = S2 * (1.f / 128.f) - mu * mu;
            mus[0] = mu;
            mus[1] = rsqrtf(var + 1e-5f);
        }
        __syncthreads();
        float yn = (y - mus[0]) * mus[1] * gg + bb;
        float z = g_z[j * 128 + d];
        gsm[d] = yn * (z / (1.f + __expf(-z)));
        __syncthreads();
        {
            float acc = 0.f;
            int base = hh2 * 64;
            #pragma unroll 8
            for (int dd = 0; dd < 64; dd++)
                acc = fmaf(Wsm[oo * 129 + base + dd], gsm[base + dd], acc);
            acc += __shfl_xor_sync(0xffffffffu, acc, 16);
            if (hh2 == 0) out[j * 64 + oo] = acc;
        }
        __syncthreads();
    }
}

// ---------------- launch ----------------
extern "C" void kernel_launch(void* const* d_in, const int* in_sizes, int n_in,
                              void* d_out, int out_size) {
    const float* x        = (const float*)d_in[0];
    const float* W_in     = (const float*)d_in[1];
    const float* conv_w   = (const float*)d_in[2];
    const float* conv_b   = (const float*)d_in[3];
    const float* x_proj_w = (const float*)d_in[4];
    const float* dt_w     = (const float*)d_in[5];
    const float* dt_b     = (const float*)d_in[6];
    const float* A_logs   = (const float*)d_in[7];
    const float* Ds       = (const float*)d_in[8];
    const float* ln_g     = (const float*)d_in[9];
    const float* ln_b     = (const float*)d_in[10];
    const float* W_out    = (const float*)d_in[11];
    float* out = (float*)d_out;

    k_inproj<<<128, 256>>>(x, W_in);
    k_conv<<<(LL * 64) / 256, 256>>>(conv_w, conv_b);
    {
        dim3 g(LL / 32, KDIR);
        k_proj<<<g, 256>>>(x_proj_w, dt_w, dt_b);
    }
    {
        dim3 gs(2, CHK, KDIR);
        k_scan1<<<gs, 1024>>>(A_logs);
        k_scan2<<<48, 256>>>();
        k_scan3<<<gs, 1024>>>(A_logs);
    }
    k_comb<<<256, 128>>>(Ds, ln_g, ln_b, W_out, out);
}

// round 7
// speedup vs baseline: 1.6190x; 1.0537x over previous
#include <cuda_runtime.h>
#include <cuda_bf16.h>
#include <math.h>

#define KDIR 6
#define LL 4096
#define DI 128
#define NS 16
#define DTR 4
#define NCH (KDIR * DI)
#define CHK 64
#define LC  (LL / CHK)         // 64

// ---------------- scratch ----------------
__device__ float  g_xx[LL * DI];
__device__ float  g_z [LL * DI];
__device__ float  g_xcT[LL * DI];
__device__ float2 g_BC[KDIR * LL * NS];   // (B,C), [k][t][n]
__device__ float2 g_dd[KDIR * DI * LL];   // (delta, delta*u), [k][d][t]
__device__ float  g_y [KDIR * LL * DI];   // [k][t][d]
__device__ float2 g_chk [NCH * CHK * NS];
__device__ float  g_init[NCH * CHK * NS];

// ---------------- closed-form diagonal permutation ----------------
__device__ __forceinline__ int dg_low(int r) {
    int dg = (int)((sqrtf((float)(8 * r + 1)) - 1.f) * 0.5f);
    while (((dg + 1) * (dg + 2)) >> 1 <= r) dg++;
    while ((dg * (dg + 1)) >> 1 > r) dg--;
    return dg;
}
__device__ __forceinline__ int diag_t(int r) {
    int i, dg;
    if (r < 2080) { dg = dg_low(r); i = r - ((dg * (dg + 1)) >> 1); }
    else {
        int q = 4095 - r;
        int dgm = dg_low(q);
        int p = q - ((dgm * (dgm + 1)) >> 1);
        i = 63 - p;
        dg = 126 - dgm;
    }
    int j = dg - i;
    return (i << 6) | j;
}
__device__ __forceinline__ int rev_idx(int t) {
    int i = t >> 6, c = t & 63, dg = i + c;
    int cum = (dg < 64) ? ((dg * (dg + 1)) >> 1)
                        : 4096 - (((127 - dg) * (128 - dg)) >> 1);
    int lo = dg - 63; if (lo < 0) lo = 0;
    return cum + i - lo;
}
__device__ __forceinline__ int sin_idx(int k, int t) {
    switch (k) {
        case 0: return t;
        case 1: return ((t & 63) << 6) | (t >> 6);
        case 2: return 4095 - t;
        case 3: { int t2 = 4095 - t; return ((t2 & 63) << 6) | (t2 >> 6); }
        case 4: return diag_t(t);
        default: return diag_t(t) ^ 63;
    }
}
__device__ __forceinline__ int iout_idx(int k, int j) {
    switch (k) {
        case 0: return j;
        case 1: return ((j & 63) << 6) | (j >> 6);
        case 2: return 4095 - j;
        case 3: return 4095 - (((j & 63) << 6) | (j >> 6));
        case 4: return rev_idx(j);
        default: return rev_idx(4095 - j);
    }
}

// ---------------- in_proj GEMM ----------------
__global__ void __launch_bounds__(256) k_inproj(const float* __restrict__ x,
                                                const float* __restrict__ W_in) {
    __shared__ float Wsm[128 * 65];
    __shared__ float xsm[32 * 65];
    int tid = threadIdx.x;
    int l0 = blockIdx.x * 32;
    for (int i = tid; i < 32 * 64; i += 256)
        xsm[(i >> 6) * 65 + (i & 63)] = x[(l0 + (i >> 6)) * 64 + (i & 63)];
    int og = tid & 31;
    int lg = tid >> 5;
    for (int ot = 0; ot < 2; ot++) {
        __syncthreads();
        for (int i = tid; i < 128 * 64; i += 256)
            Wsm[(i >> 6) * 65 + (i & 63)] = W_in[(ot * 128 + (i >> 6)) * 64 + (i & 63)];
        __syncthreads();
        float acc[4][4];
        #pragma unroll
        for (int i = 0; i < 4; i++)
            #pragma unroll
            for (int ii = 0; ii < 4; ii++) acc[i][ii] = 0.f;
        for (int c = 0; c < 64; c++) {
            float wv[4], xv[4];
            #pragma unroll
            for (int i = 0; i < 4; i++)  wv[i]  = Wsm[(og + 32 * i) * 65 + c];
            #pragma unroll
            for (int ii = 0; ii < 4; ii++) xv[ii] = xsm[(lg + 8 * ii) * 65 + c];
            #pragma unroll
            for (int i = 0; i < 4; i++)
                #pragma unroll
                for (int ii = 0; ii < 4; ii++)
                    acc[i][ii] = fmaf(wv[i], xv[ii], acc[i][ii]);
        }
        float* dst = (ot == 0) ? g_xx : g_z;
        #pragma unroll
        for (int i = 0; i < 4; i++)
            #pragma unroll
            for (int ii = 0; ii < 4; ii++)
                dst[(l0 + lg + 8 * ii) * 128 + og + 32 * i] = acc[i][ii];
    }
}

// ---------------- depthwise 3x3 conv + bias + SiLU ----------------
__global__ void __launch_bounds__(256) k_conv(const float* __restrict__ conv_w,
                                              const float* __restrict__ conv_b) {
    __shared__ float2 cw[9 * 64];
    __shared__ float2 cb[64];
    int tid = threadIdx.x;
    for (int i = tid; i < 9 * 64; i += 256) {
        int tap = i >> 6, d2 = i & 63;
        cw[i] = make_float2(conv_w[(2 * d2) * 9 + tap], conv_w[(2 * d2 + 1) * 9 + tap]);
    }
    if (tid < 64) cb[tid] = ((const float2*)conv_b)[tid];
    __syncthreads();
    int idx = blockIdx.x * 256 + tid;
    int d2 = idx & 63;
    int l = idx >> 6;
    int h = l >> 6, w = l & 63;
    float2 acc = cb[d2];
    const float2* xx2 = (const float2*)g_xx;
    #pragma unroll
    for (int kh = -1; kh <= 1; kh++) {
        int hh = h + kh;
        if ((unsigned)hh >= 64u) continue;
        #pragma unroll
        for (int kw = -1; kw <= 1; kw++) {
            int wc = w + kw;
            if ((unsigned)wc >= 64u) continue;
            float2 v = xx2[((hh << 6) | wc) * 64 + d2];
            float2 cc = cw[((kh + 1) * 3 + (kw + 1)) * 64 + d2];
            acc.x = fmaf(cc.x, v.x, acc.x);
            acc.y = fmaf(cc.y, v.y, acc.y);
        }
    }
    acc.x = acc.x / (1.f + __expf(-acc.x));
    acc.y = acc.y / (1.f + __expf(-acc.y));
    ((float2*)g_xcT)[l * 64 + d2] = acc;
}

// ---------------- projection + fused delta ----------------
__global__ void __launch_bounds__(256) k_proj(const float* __restrict__ x_proj_w,
                                              const float* __restrict__ dt_w,
                                              const float* __restrict__ dt_b) {
    __shared__ float xs[32][129];
    __shared__ float Ps[36 * 128];
    __shared__ float dts[4][32];
    __shared__ int sidx[32];
    int k  = blockIdx.y;
    int t0 = blockIdx.x * 32;
    int tid = threadIdx.x;
    if (tid < 32) sidx[tid] = sin_idx(k, t0 + tid);
    __syncthreads();
    for (int i = tid; i < 36 * 128; i += 256)
        Ps[i] = x_proj_w[k * 36 * 128 + i];
    {
        int lane = tid & 31;
        for (int r = tid >> 5; r < 32; r += 8) {
            int s = sidx[r];
            const float4* src = (const float4*)(g_xcT + s * 128);
            float4 v = src[lane];
            xs[r][lane * 4 + 0] = v.x;
            xs[r][lane * 4 + 1] = v.y;
            xs[r][lane * 4 + 2] = v.z;
            xs[r][lane * 4 + 3] = v.w;
        }
    }
    __syncthreads();
    if (tid < 192) {
        int cg = tid >> 4;
        int tg = tid & 15;
        float acc[3][2] = {{0.f,0.f},{0.f,0.f},{0.f,0.f}};
        for (int dd = 0; dd < 128; dd++) {
            float b0 = xs[tg * 2 + 0][dd];
            float b1 = xs[tg * 2 + 1][dd];
            #pragma unroll
            for (int i = 0; i < 3; i++) {
                float a = Ps[(cg * 3 + i) * 128 + dd];
                acc[i][0] = fmaf(a, b0, acc[i][0]);
                acc[i][1] = fmaf(a, b1, acc[i][1]);
            }
        }
        #pragma unroll
        for (int i = 0; i < 3; i++)
            #pragma unroll
            for (int j = 0; j < 2; j++) {
                int c = cg * 3 + i;
                int tl = tg * 2 + j;
                int t = t0 + tl;
                float v = acc[i][j];
                if (c < 4)       dts[c][tl] = v;
                else if (c < 20) g_BC[(size_t)(k * LL + t) * NS + (c - 4)].x = v;
                else             g_BC[(size_t)(k * LL + t) * NS + (c - 20)].y = v;
            }
    }
    __syncthreads();
    {
        int t = tid & 31;
        int w = tid >> 5;
        #pragma unroll
        for (int it = 0; it < 16; it++) {
            int d = w + 8 * it;
            float acc = dt_b[k * 128 + d];
            #pragma unroll
            for (int r = 0; r < 4; r++)
                acc = fmaf(dt_w[(k * 128 + d) * 4 + r], dts[r][t], acc);
            float delta = (acc > 20.f) ? acc : log1pf(__expf(acc));
            float u = xs[t][d];
            g_dd[(size_t)(k * 128 + d) * LL + t0 + t] = make_float2(delta, delta * u);
        }
    }
}

// ---------------- scan pass 1: per-chunk (xf, aprod), float4 dd ----------------
__global__ void __launch_bounds__(512) k_scan1(const float* __restrict__ A_logs) {
    int tid = threadIdx.x;
    int wl = tid >> 5;
    int ln = tid & 31;
    int k = blockIdx.z, chunk = blockIdx.y, xh = blockIdx.x;
    int dp = xh * 16 + wl;
    int half = ln >> 4, n = ln & 15;
    int d = dp + (half << 6);
    int ch = k * 128 + d;
    int tbeg = chunk * LC;

    const float2* pBC = g_BC + (size_t)(k * LL + tbeg) * NS + n;
    const float4* pDD4 = (const float4*)(g_dd + (size_t)ch * LL + tbeg);
    float cA = -expf(A_logs[ch * 16 + n]) * 1.44269504f;
    float x = 0.f, sdelta = 0.f;
    #pragma unroll 4
    for (int s2 = 0; s2 < LC / 2; s2++) {
        float4 q = pDD4[s2];
        float b0 = pBC[(size_t)(2 * s2) * NS].x;
        float b1 = pBC[(size_t)(2 * s2 + 1) * NS].x;
        float dA0, dA1;
        asm("ex2.approx.ftz.f32 %0, %1;" : "=f"(dA0) : "f"(q.x * cA));
        x = fmaf(dA0, x, q.y * b0);
        asm("ex2.approx.ftz.f32 %0, %1;" : "=f"(dA1) : "f"(q.z * cA));
        x = fmaf(dA1, x, q.w * b1);
        sdelta += q.x + q.z;
    }
    float ap;
    asm("ex2.approx.ftz.f32 %0, %1;" : "=f"(ap) : "f"(sdelta * cA));
    g_chk[((size_t)ch * CHK + chunk) * NS + n] = make_float2(x, ap);
}

// ---------------- scan pass 2: chunk summaries -> initial states ----------------
__global__ void k_scan2() {
    int idx = blockIdx.x * 256 + threadIdx.x;
    if (idx >= NCH * NS) return;
    int ch = idx >> 4;
    int n  = idx & 15;
    float carry = 0.f;
    #pragma unroll 8
    for (int c = 0; c < CHK; c++) {
        size_t off = ((size_t)ch * CHK + c) * NS + n;
        float2 f = g_chk[off];
        g_init[off] = carry;
        carry = fmaf(f.y, carry, f.x);
    }
}

// ---------------- scan pass 3: smem transpose-reduce, coalesced y ----------------
__global__ void __launch_bounds__(1024) k_scan3(const float* __restrict__ A_logs) {
    __shared__ float xc[32][8][33];
    __shared__ float ytile[8 * 65];
    int tid = threadIdx.x;
    int wl = tid >> 5;
    int ln = tid & 31;
    int k = blockIdx.z, chunk = blockIdx.y, xh = blockIdx.x;
    int dp = xh * 32 + wl;
    int half = ln >> 4, n = ln & 15;
    int d = dp + (half << 6);
    int ch = k * 128 + d;
    int tbeg = chunk * LC;

    const float2* pBC = g_BC + (size_t)(k * LL + tbeg) * NS + n;
    const float4* pDD4 = (const float4*)(g_dd + (size_t)ch * LL + tbeg);
    float cA = -expf(A_logs[ch * 16 + n]) * 1.44269504f;
    float x = g_init[((size_t)ch * CHK + chunk) * NS + n];

    int rc = ln >> 4;
    int rj = (ln >> 1) & 7;
    int rh = ln & 1;
    int sr = tid >> 6;
    int sc = tid & 63;
    int sd = xh * 32 + (sc & 31) + ((sc >> 5) << 6);
    float* ydst0 = g_y + (size_t)(k * LL + tbeg) * 128 + sd;

    for (int t0 = 0; t0 < LC; t0 += 8) {
        #pragma unroll
        for (int s2 = 0; s2 < 4; s2++) {
            float4 q = pDD4[(t0 >> 1) + s2];
            int s = 2 * s2;
            float2 bc0 = pBC[(size_t)(t0 + s) * NS];
            float2 bc1 = pBC[(size_t)(t0 + s + 1) * NS];
            float dA0, dA1;
            asm("ex2.approx.ftz.f32 %0, %1;" : "=f"(dA0) : "f"(q.x * cA));
            x = fmaf(dA0, x, q.y * bc0.x);
            xc[wl][s][ln] = x * bc0.y;
            asm("ex2.approx.ftz.f32 %0, %1;" : "=f"(dA1) : "f"(q.z * cA));
            x = fmaf(dA1, x, q.w * bc1.x);
            xc[wl][s + 1][ln] = x * bc1.y;
        }
        __syncwarp();
        float sum = 0.f;
        #pragma unroll
        for (int m = 0; m < 8; m++)
            sum += xc[wl][rj][rc * 16 + rh * 8 + m];
        sum += __shfl_xor_sync(0xffffffffu, sum, 1);
        if (rh == 0) ytile[rj * 65 + rc * 32 + wl] = sum;
        __syncthreads();
        if (tid < 512) ydst0[(size_t)(t0 + sr) * 128] = ytile[sr * 65 + sc];
        __syncthreads();
    }
}

// ---------------- combine: 4 concurrent positions per block ----------------
__global__ void __launch_bounds__(512) k_comb(const float* __restrict__ Ds,
                                              const float* __restrict__ ln_g,
                                              const float* __restrict__ ln_b,
                                              const float* __restrict__ W_out,
                                              float* __restrict__ out) {
    __shared__ float Wsm[64 * 129];
    __shared__ float gsm[4][132];
    __shared__ float red[4][8];
    __shared__ float mus[4][2];
    __shared__ int ism[6 * 16];
    int tid = threadIdx.x;
    int g = tid >> 7;
    int gt = tid & 127;
    for (int i = tid; i < 64 * 128; i += 512)
        Wsm[(i >> 7) * 129 + (i & 127)] = W_out[i];
    if (tid < 96) {
        int kk = tid >> 4, jj = tid & 15;
        ism[kk * 16 + jj] = iout_idx(kk, blockIdx.x * 16 + jj);
    }
    int d = gt;
    float dsum = 0.f;
    #pragma unroll
    for (int k = 0; k < 5; k++) dsum += Ds[k * 128 + d];
    float d5 = Ds[5 * 128 + d];
    float gg = ln_g[d], bb = ln_b[d];
    int lane = tid & 31;
    int wg = gt >> 5;                        // warp within group 0..3
    int oo = (wg << 4) + (lane & 15);        // output 0..63
    int hh2 = lane >> 4;
    __syncthreads();

    for (int it = 0; it < 4; it++) {
        int jj = it * 4 + g;
        int j = blockIdx.x * 16 + jj;
        float y = 0.f;
        #pragma unroll
        for (int k = 0; k < 6; k++)
            y += g_y[(size_t)(k * LL + ism[k * 16 + jj]) * 128 + d];
        int fl = ((63 - (j >> 6)) << 6) | (j & 63);
        y += dsum * g_xcT[j * 128 + d] + d5 * g_xcT[fl * 128 + d];
        float s1 = y, s2 = y * y;
        #pragma unroll
        for (int o = 16; o; o >>= 1) {
            s1 += __shfl_xor_sync(0xffffffffu, s1, o);
            s2 += __shfl_xor_sync(0xffffffffu, s2, o);
        }
        if (lane == 0) { red[g][wg] = s1; red[g][4 + wg] = s2; }
        __syncthreads();
        if (gt == 0) {
            float S1 = red[g][0] + red[g][1] + red[g][2] + red[g][3];
            float S2 = red[g][4] + red[g][5] + red[g][6] + red[g][7];
            float mu = S1 * (1.f / 128.f);
            float var = S2 * (1.f / 128.f) - mu * mu;
            mus[g][0] = mu;
            mus[g][1] = rsqrtf(var + 1e-5f);
        }
        __syncthreads();
        float yn = (y - mus[g][0]) * mus[g][1] * gg + bb;
        float z = g_z[j * 128 + d];
        gsm[g][d] = yn * (z / (1.f + __expf(-z)));
        __syncthreads();
        {
            float acc = 0.f;
            int base = hh2 << 6;
            #pragma unroll 8
            for (int dd = 0; dd < 64; dd++) {
                int c = (dd + (hh2 << 4)) & 63;   // stagger half 1 to avoid bank conflicts
                acc = fmaf(Wsm[oo * 129 + base + c], gsm[g][base + c], acc);
            }
            acc += __shfl_xor_sync(0xffffffffu, acc, 16);
            if (hh2 == 0) out[j * 64 + oo] = acc;
        }
        __syncthreads();
    }
}

// ---------------- launch ----------------
extern "C" void kernel_launch(void* const* d_in, const int* in_sizes, int n_in,
                              void* d_out, int out_size) {
    const float* x        = (const float*)d_in[0];
    const float* W_in     = (const float*)d_in[1];
    const float* conv_w   = (const float*)d_in[2];
    const float* conv_b   = (const float*)d_in[3];
    const float* x_proj_w = (const float*)d_in[4];
    const float* dt_w     = (const float*)d_in[5];
    const float* dt_b     = (const float*)d_in[6];
    const float* A_logs   = (const float*)d_in[7];
    const float* Ds       = (const float*)d_in[8];
    const float* ln_g     = (const float*)d_in[9];
    const float* ln_b     = (const float*)d_in[10];
    const float* W_out    = (const float*)d_in[11];
    float* out = (float*)d_out;

    k_inproj<<<128, 256>>>(x, W_in);
    k_conv<<<(LL * 64) / 256, 256>>>(conv_w, conv_b);
    {
        dim3 g(LL / 32, KDIR);
        k_proj<<<g, 256>>>(x_proj_w, dt_w, dt_b);
    }
    {
        dim3 g1(4, CHK, KDIR);
        k_scan1<<<g1, 512>>>(A_logs);
        k_scan2<<<48, 256>>>();
        dim3 g3(2, CHK, KDIR);
        k_scan3<<<g3, 1024>>>(A_logs);
    }
    k_comb<<<256, 512>>>(Ds, ln_g, ln_b, W_out, out);
}